// round 6
// baseline (speedup 1.0000x reference)
#include <cuda_runtime.h>
#include <cuda_fp16.h>
#include <cstdint>

#define Bn 16
#define Fn 257
#define FPAD 272
#define Tn 8000
#define NBn 64
#define TTILE 128
#define KSTEPS 17

// ---- scan config ----
#define NCH 8
#define CHUNK 1000
#define WARM 256
#define LOCAL (WARM + CHUNK)      // 1256 live local steps
#define STILE 64                  // t per tile
#define NTILE 20                  // ceil(1280/64)
#define ROWST 66                  // smem row stride (floats), 264B (8B aligned)
#define O2ST 34                   // out-stage row stride (half2 units)
#define BUF0 0
#define BUF1 (256 * ROWST)
#define O2OFF (2 * 256 * ROWST)
#define SCAN_SMEM ((2 * 256 * ROWST + 256 * O2ST) * 4)  // 169984 B

// ---- band GEMM config ----
#define AST 136
#define BST 280
#define OST 132
#define A_BYTES (FPAD * AST * 2)
#define B_BYTES (NBn * BST * 2)
#define SMEM_TOTAL (A_BYTES + B_BYTES)

// 65.8 MB fp16 scratch: g_vnr[b][f][t] = 0.1 * vnr (t-contiguous)
__device__ __align__(128) __half g_vnr[(size_t)Bn * Fn * Tn];

__device__ __forceinline__ uint32_t smem_u32(const void* p) {
    uint32_t a;
    asm("{ .reg .u64 t; cvta.to.shared.u64 t, %1; cvt.u32.u64 %0, t; }" : "=r"(a) : "l"(p));
    return a;
}
__device__ __forceinline__ void cpasync8(uint32_t dst, const void* src, int sz) {
    asm volatile("cp.async.ca.shared.global [%0], [%1], 8, %2;" :: "r"(dst), "l"(src), "r"(sz));
}
__device__ __forceinline__ void cp_commit() { asm volatile("cp.async.commit_group;" ::: "memory"); }
__device__ __forceinline__ void cp_wait0()  { asm volatile("cp.async.wait_group 0;" ::: "memory"); }

__device__ __forceinline__ void ldsm_x4_t(uint32_t a[4], uint32_t addr) {
    asm volatile("ldmatrix.sync.aligned.m8n8.x4.trans.shared.b16 {%0,%1,%2,%3}, [%4];"
        : "=r"(a[0]), "=r"(a[1]), "=r"(a[2]), "=r"(a[3]) : "r"(addr));
}
__device__ __forceinline__ void ldsm_x4(uint32_t a[4], uint32_t addr) {
    asm volatile("ldmatrix.sync.aligned.m8n8.x4.shared.b16 {%0,%1,%2,%3}, [%4];"
        : "=r"(a[0]), "=r"(a[1]), "=r"(a[2]), "=r"(a[3]) : "r"(addr));
}
__device__ __forceinline__ void mma16816(float d[4], const uint32_t a[4], uint32_t b0, uint32_t b1) {
    asm volatile("mma.sync.aligned.m16n8k16.row.col.f32.f16.f16.f32 "
        "{%0,%1,%2,%3}, {%4,%5,%6,%7}, {%8,%9}, {%0,%1,%2,%3};"
        : "+f"(d[0]), "+f"(d[1]), "+f"(d[2]), "+f"(d[3])
        : "r"(a[0]), "r"(a[1]), "r"(a[2]), "r"(a[3]), "r"(b0), "r"(b1));
}
__device__ __forceinline__ float tanh_fast(float x) {
    float y; asm("tanh.approx.f32 %0, %1;" : "=f"(y) : "f"(x)); return y;
}

__device__ __forceinline__ float nf_step(float x, float nf, float rise, float fall, float fl) {
    float d  = x - nf;
    float cr = fmaf(rise, d, nf);
    float cf = fmaf(fall, d, nf);
    return fmaxf(fmaxf(cr, cf), fl);
}

// ============================================================
// K1: smem-staged transposed scan -> g_vnr fp16 (0.1 * vnr)
// ============================================================
extern __shared__ float s_scan[];

__global__ __launch_bounds__(256, 1) void scan_kernel(
    const float* __restrict__ mag,
    const float* __restrict__ p_ns,
    const float* __restrict__ p_rr,
    const float* __restrict__ p_rf)
{
    const int bb = blockIdx.x / 9;
    const int fg = blockIdx.x % 9;
    const int tid = threadIdx.x;
    const int c = tid >> 5;       // chunk (warp)
    const int l = tid & 31;       // chain lane

    const uint32_t sbase = smem_u32(s_scan);

    const float rise = 1.0f / (1.0f + expf(-__ldg(p_rr)));
    const float fall = 1.0f / (1.0f + expf(-__ldg(p_rf)));
    const float ns   = fabsf(__ldg(p_ns));

    const int fmine = fg * 32 + l;
    const bool fvalid = (fmine < Fn);
    const size_t myrow = ((size_t)bb * Fn + (fvalid ? fmine : Fn - 1)) * Tn;

    float nf = 1.0f, fl_ = 0.0f;
    if (fvalid) {
        float mn = 3.4e38f;
        #pragma unroll
        for (int i = 0; i < 20; ++i) mn = fminf(mn, __ldg(mag + myrow + i));
        mn = fmaxf(mn, 1e-5f);
        nf = mn; fl_ = 0.5f * mn;
    }

    const int t0base = c * CHUNK - WARM;

    #define ISSUE_TILE(k, sel) { \
        const int t0g = t0base + (k) * STILE; \
        const int tt = t0g + 2 * l; \
        const int szl = (tt >= 0 && tt < Tn - 1) ? 8 : 0; \
        const int ttc = min(max(tt, 0), Tn - 2); \
        const uint32_t dbase = sbase + (uint32_t)((((sel) ? BUF1 : BUF0) + (c * 32) * ROWST + 2 * l) * 4); \
        _Pragma("unroll") \
        for (int m = 0; m < 32; ++m) { \
            const int fm = fg * 32 + m; \
            const int szm = (fm < Fn) ? szl : 0; \
            const float* src = mag + ((size_t)bb * Fn + ((fm < Fn) ? fm : Fn - 1)) * Tn + ttc; \
            cpasync8(dbase + (uint32_t)(m * ROWST * 4), src, szm); \
        } }

    ISSUE_TILE(0, 0);
    cp_commit();

    float* o2f = s_scan + O2OFF;
    __half2 pend = __floats2half2_rn(0.f, 0.f);

    for (int k = 0; k < NTILE; ++k) {
        cp_wait0();
        __syncthreads();
        if (k + 1 < NTILE) { ISSUE_TILE(k + 1, (k + 1) & 1); }
        cp_commit();

        const float* srow = s_scan + ((k & 1) ? BUF1 : BUF0) + (c * 32 + l) * ROWST;
        float* orow = o2f + (c * 32 + l) * O2ST;

        #pragma unroll 8
        for (int j = 0; j < STILE; ++j) {
            const int i = k * STILE + j;
            if (i >= LOCAL) break;
            float x = srow[j];
            if (c > 0 || i >= WARM) {
                nf = nf_step(x, nf, rise, fall, fl_);
                if (i >= WARM) {
                    float o = __fdividef(x, fmaf(ns, nf, 1e-8f)) * 0.1f;
                    __half h = __float2half_rn(o);
                    if ((j & 1) == 0) {
                        pend = __half2half2(h);
                    } else {
                        pend = __halves2half2(__low2half(pend), h);
                        *reinterpret_cast<__half2*>(&orow[j >> 1]) = pend;
                    }
                }
            }
        }
        __syncthreads();

        if (k >= WARM / STILE) {
            const int ibase = k * STILE;
            const int ipair = ibase + 2 * l;
            if (ipair >= WARM && ipair < LOCAL) {
                #pragma unroll
                for (int m = 0; m < 32; ++m) {
                    const int fm = fg * 32 + m;
                    if (fm < Fn) {
                        __half2 h = *reinterpret_cast<__half2*>(&o2f[(c * 32 + m) * O2ST + l]);
                        const int tg = c * CHUNK + (ipair - WARM);
                        *reinterpret_cast<__half2*>(
                            g_vnr + ((size_t)bb * Fn + fm) * Tn + tg) = h;
                    }
                }
            }
        }
    }
    #undef ISSUE_TILE
}

// ============================================================
// K2: HMMA band GEMM (unchanged, proven at 68us)
// ============================================================
extern __shared__ char k2_smem[];

__global__ __launch_bounds__(256, 2) void band_kernel(
    const float* __restrict__ fb, float* __restrict__ out)
{
    const int b   = blockIdx.y;
    const int t0  = blockIdx.x * TTILE;
    const int tid = threadIdx.x;
    const int wid = tid >> 5;
    const int lane = tid & 31;

    __half* As = reinterpret_cast<__half*>(k2_smem);
    __half* Bs = reinterpret_cast<__half*>(k2_smem + A_BYTES);
    const uint32_t As_u = smem_u32(As);
    const uint32_t Bs_u = smem_u32(Bs);

    for (int i = tid; i < FPAD * 16; i += 256) {
        int f = i >> 4;
        int c = (i & 15);
        int t = t0 + c * 8;
        uint4 v = make_uint4(0u, 0u, 0u, 0u);
        if (f < Fn && t + 8 <= Tn)
            v = *reinterpret_cast<const uint4*>(g_vnr + ((size_t)b * Fn + f) * Tn + t);
        *reinterpret_cast<uint4*>(As + f * AST + c * 8) = v;
    }
    for (int i = tid; i < NBn * (BST / 8); i += 256) {
        int n  = i / (BST / 8);
        int f0 = (i % (BST / 8)) * 8;
        __half h[8];
        #pragma unroll
        for (int j = 0; j < 8; ++j) {
            int f = f0 + j;
            h[j] = (f < Fn) ? __float2half_rn(__ldg(fb + n * Fn + f)) : __float2half_rn(0.0f);
        }
        *reinterpret_cast<uint4*>(Bs + n * BST + f0) = *reinterpret_cast<uint4*>(h);
    }
    __syncthreads();

    const int m0 = wid * 16;
    const int krow = (lane & 7) + ((lane >> 4) << 3);
    const int msel = ((lane >> 3) & 1) * 8;
    const uint32_t a_addr0 = As_u + (uint32_t)((krow * AST + m0 + msel) * 2);

    const int nrow = (lane & 7) + ((lane >> 4) << 3);
    const int ksel = ((lane >> 3) & 1) * 8;
    uint32_t b_addr0[4];
    #pragma unroll
    for (int j2 = 0; j2 < 4; ++j2)
        b_addr0[j2] = Bs_u + (uint32_t)(((j2 * 16 + nrow) * BST + ksel) * 2);

    float d[8][4];
    #pragma unroll
    for (int j = 0; j < 8; ++j)
        #pragma unroll
        for (int q = 0; q < 4; ++q) d[j][q] = 0.0f;

    for (int ks = 0; ks < KSTEPS; ++ks) {
        uint32_t a[4];
        ldsm_x4_t(a, a_addr0 + (uint32_t)(ks * 16 * AST * 2));
        #pragma unroll
        for (int j2 = 0; j2 < 4; ++j2) {
            uint32_t bbv[4];
            ldsm_x4(bbv, b_addr0[j2] + (uint32_t)(ks * 32));
            mma16816(d[j2 * 2],     a, bbv[0], bbv[1]);
            mma16816(d[j2 * 2 + 1], a, bbv[2], bbv[3]);
        }
    }

    __syncthreads();
    float* stg = reinterpret_cast<float*>(k2_smem);
    const int g  = lane >> 2;
    const int tp = lane & 3;
    #pragma unroll
    for (int j = 0; j < 8; ++j) {
        int n = j * 8 + 2 * tp;
        int t = m0 + g;
        stg[n * OST + t]           = d[j][0];
        stg[(n + 1) * OST + t]     = d[j][1];
        stg[n * OST + t + 8]       = d[j][2];
        stg[(n + 1) * OST + t + 8] = d[j][3];
    }
    __syncthreads();

    const int tmax = Tn - t0;
    float* ob = out + (size_t)b * NBn * Tn + t0;
    #pragma unroll
    for (int it = 0; it < 8; ++it) {
        int idx = tid + it * 256;
        int n = idx >> 5;
        int c = (idx & 31) * 4;
        if (c < tmax) {
            float4 v = *reinterpret_cast<float4*>(stg + n * OST + c);
            v.x = tanh_fast(v.x); v.y = tanh_fast(v.y);
            v.z = tanh_fast(v.z); v.w = tanh_fast(v.w);
            *reinterpret_cast<float4*>(ob + (size_t)n * Tn + c) = v;
        }
    }
}

// ============================================================
extern "C" void kernel_launch(void* const* d_in, const int* in_sizes, int n_in,
                              void* d_out, int out_size)
{
    const float* mag = (const float*)d_in[0];
    const float* fb  = (const float*)d_in[1];
    const float* ns  = (const float*)d_in[2];
    const float* rr  = (const float*)d_in[3];
    const float* rf  = (const float*)d_in[4];
    float* out = (float*)d_out;

    cudaFuncSetAttribute(scan_kernel, cudaFuncAttributeMaxDynamicSharedMemorySize, SCAN_SMEM);
    cudaFuncSetAttribute(band_kernel, cudaFuncAttributeMaxDynamicSharedMemorySize, SMEM_TOTAL);

    scan_kernel<<<Bn * 9, 256, SCAN_SMEM>>>(mag, ns, rr, rf);

    dim3 grid((Tn + TTILE - 1) / TTILE, Bn);
    band_kernel<<<grid, 256, SMEM_TOTAL>>>(fb, out);
}

// round 7
// speedup vs baseline: 1.6624x; 1.6624x over previous
#include <cuda_runtime.h>
#include <cuda_fp16.h>
#include <cstdint>

#define Bn 16
#define Fn 257
#define FPAD 272
#define Tn 8000
#define NBn 64
#define CHUNK 400
#define NCH 20
#define WARM 256
#define TTILE 128
#define KSTEPS 17

#define AST 136           // A smem stride (halves)
#define BST 280           // B smem/global stride (halves)
#define OST 132           // out-stage stride (floats)
#define A_BYTES (FPAD * AST * 2)
#define B_BYTES (NBn * BST * 2)
#define SMEM_TOTAL (A_BYTES + B_BYTES)

// 65.8 MB fp16 scratch: g_vnr[b][f][t] = 0.1 * vnr (t-contiguous)
__device__ __align__(128) __half g_vnr[(size_t)Bn * Fn * Tn];
// pre-converted fp16 filterbank, padded [64][280]
__device__ __align__(128) __half g_fbh[NBn * BST];

struct __align__(8) H4 { __half2 a, b; };

__device__ __forceinline__ uint32_t smem_u32(const void* p) {
    uint32_t a;
    asm("{ .reg .u64 t; cvta.to.shared.u64 t, %1; cvt.u32.u64 %0, t; }" : "=r"(a) : "l"(p));
    return a;
}
__device__ __forceinline__ void cpasync16(uint32_t dst, const void* src, int sz) {
    asm volatile("cp.async.ca.shared.global [%0], [%1], 16, %2;" :: "r"(dst), "l"(src), "r"(sz));
}
__device__ __forceinline__ void cp_commit() { asm volatile("cp.async.commit_group;" ::: "memory"); }
__device__ __forceinline__ void cp_wait0()  { asm volatile("cp.async.wait_group 0;" ::: "memory"); }

__device__ __forceinline__ void ldsm_x4_t(uint32_t a[4], uint32_t addr) {
    asm volatile("ldmatrix.sync.aligned.m8n8.x4.trans.shared.b16 {%0,%1,%2,%3}, [%4];"
        : "=r"(a[0]), "=r"(a[1]), "=r"(a[2]), "=r"(a[3]) : "r"(addr));
}
__device__ __forceinline__ void ldsm_x4(uint32_t a[4], uint32_t addr) {
    asm volatile("ldmatrix.sync.aligned.m8n8.x4.shared.b16 {%0,%1,%2,%3}, [%4];"
        : "=r"(a[0]), "=r"(a[1]), "=r"(a[2]), "=r"(a[3]) : "r"(addr));
}
__device__ __forceinline__ void mma16816(float d[4], const uint32_t a[4], uint32_t b0, uint32_t b1) {
    asm volatile("mma.sync.aligned.m16n8k16.row.col.f32.f16.f16.f32 "
        "{%0,%1,%2,%3}, {%4,%5,%6,%7}, {%8,%9}, {%0,%1,%2,%3};"
        : "+f"(d[0]), "+f"(d[1]), "+f"(d[2]), "+f"(d[3])
        : "r"(a[0]), "r"(a[1]), "r"(a[2]), "r"(a[3]), "r"(b0), "r"(b1));
}
__device__ __forceinline__ float tanh_fast(float x) {
    float y; asm("tanh.approx.f32 %0, %1;" : "=f"(y) : "f"(x)); return y;
}

__device__ __forceinline__ float nf_step(float x, float nf, float rise, float fall, float fl) {
    float d  = x - nf;
    float cr = fmaf(rise, d, nf);
    float cf = fmaf(fall, d, nf);
    return fmaxf(fmaxf(cr, cf), fl);
}

// ============================================================
// K0: one-time fb fp32 -> fp16 (padded to BST with zeros)
// ============================================================
__global__ __launch_bounds__(256) void fbconv_kernel(const float* __restrict__ fb)
{
    for (int i = threadIdx.x + blockIdx.x * 256; i < NBn * BST; i += 256 * 8) {
        int n = i / BST;
        int f = i - n * BST;
        g_fbh[i] = (f < Fn) ? __float2half_rn(__ldg(fb + n * Fn + f)) : __float2half_rn(0.0f);
    }
}

// ============================================================
// K1: chunked noise-floor scan -> fp16 scratch [b][f][t] (0.1 * vnr)
// (round-4 proven version)
// ============================================================
__global__ __launch_bounds__(256) void scan_kernel(
    const float* __restrict__ mag,
    const float* __restrict__ p_ns,
    const float* __restrict__ p_rr,
    const float* __restrict__ p_rf)
{
    int tid = blockIdx.x * 256 + threadIdx.x;
    if (tid >= Bn * Fn * NCH) return;
    int chunk = tid % NCH;
    int chain = tid / NCH;

    float rise = 1.0f / (1.0f + expf(-__ldg(p_rr)));
    float fall = 1.0f / (1.0f + expf(-__ldg(p_rf)));
    float ns   = fabsf(__ldg(p_ns));

    size_t base = (size_t)chain * Tn;
    const float4* gm = reinterpret_cast<const float4*>(mag + base);
    H4* gv = reinterpret_cast<H4*>(g_vnr + base);

    float mn = 3.4e38f;
    #pragma unroll
    for (int i = 0; i < 20; ++i) mn = fminf(mn, __ldg(mag + base + i));
    mn = fmaxf(mn, 1e-5f);
    const float fl = 0.5f * mn;
    float nf = mn;

    int t0 = chunk * CHUNK;
    int tw = (chunk == 0) ? 0 : (t0 - WARM);

    for (int q = (tw >> 2); q < (t0 >> 2); ++q) {
        float4 v = gm[q];
        nf = nf_step(v.x, nf, rise, fall, fl);
        nf = nf_step(v.y, nf, rise, fall, fl);
        nf = nf_step(v.z, nf, rise, fall, fl);
        nf = nf_step(v.w, nf, rise, fall, fl);
    }

    const int q0 = t0 >> 2;
    float4 b0 = gm[q0], b1 = gm[q0 + 1], b2 = gm[q0 + 2], b3 = gm[q0 + 3];

    #define EMIT4(c, idx) { \
        float o0, o1, o2, o3; \
        nf = nf_step(c.x, nf, rise, fall, fl); o0 = __fdividef(c.x, fmaf(ns, nf, 1e-8f)) * 0.1f; \
        nf = nf_step(c.y, nf, rise, fall, fl); o1 = __fdividef(c.y, fmaf(ns, nf, 1e-8f)) * 0.1f; \
        nf = nf_step(c.z, nf, rise, fall, fl); o2 = __fdividef(c.z, fmaf(ns, nf, 1e-8f)) * 0.1f; \
        nf = nf_step(c.w, nf, rise, fall, fl); o3 = __fdividef(c.w, fmaf(ns, nf, 1e-8f)) * 0.1f; \
        H4 st; st.a = __floats2half2_rn(o0, o1); st.b = __floats2half2_rn(o2, o3); \
        gv[idx] = st; }

    for (int i = 0; i < CHUNK / 4; i += 4) {
        float4 c0 = b0, c1 = b1, c2 = b2, c3 = b3;
        if (i + 8 <= CHUNK / 4) {
            b0 = gm[q0 + i + 4]; b1 = gm[q0 + i + 5];
            b2 = gm[q0 + i + 6]; b3 = gm[q0 + i + 7];
        }
        EMIT4(c0, q0 + i);
        EMIT4(c1, q0 + i + 1);
        EMIT4(c2, q0 + i + 2);
        EMIT4(c3, q0 + i + 3);
    }
    #undef EMIT4
}

// ============================================================
// K2: HMMA band GEMM.  cp.async A-tile, preconverted fp16 fb.
// ============================================================
extern __shared__ char k2_smem[];

__global__ __launch_bounds__(256, 2) void band_kernel(float* __restrict__ out)
{
    const int b   = blockIdx.y;
    const int t0  = blockIdx.x * TTILE;
    const int tid = threadIdx.x;
    const int wid = tid >> 5;
    const int lane = tid & 31;

    __half* As = reinterpret_cast<__half*>(k2_smem);             // [FPAD][AST]
    __half* Bs = reinterpret_cast<__half*>(k2_smem + A_BYTES);   // [NBn][BST]
    const uint32_t As_u = smem_u32(As);
    const uint32_t Bs_u = smem_u32(Bs);

    // ---- A tile via cp.async.16 (zero-fill pad rows / tail) ----
    const size_t vbase = (size_t)b * Fn * Tn;
    #pragma unroll
    for (int it = 0; it < 17; ++it) {
        int i = tid + it * 256;
        int f = i >> 4;
        int c = i & 15;
        int t = t0 + c * 8;
        int sz = (f < Fn && t + 8 <= Tn) ? 16 : 0;
        int fc = (f < Fn) ? f : 0;
        int tc = (t + 8 <= Tn) ? t : 0;
        cpasync16(As_u + (uint32_t)((f * AST + c * 8) * 2),
                  g_vnr + vbase + (size_t)fc * Tn + tc, sz);
    }
    // ---- B tile: preconverted fp16, coalesced uint4 copies ----
    {
        const uint4* src = reinterpret_cast<const uint4*>(g_fbh);
        uint4* dst = reinterpret_cast<uint4*>(Bs);
        #pragma unroll
        for (int it = 0; it < 9; ++it) {
            int i = tid + it * 256;
            if (i < NBn * BST / 8) dst[i] = src[i];
        }
    }
    cp_commit();
    cp_wait0();
    __syncthreads();

    const int m0 = wid * 16;
    const int krow = (lane & 7) + ((lane >> 4) << 3);
    const int msel = ((lane >> 3) & 1) * 8;
    const uint32_t a_addr0 = As_u + (uint32_t)((krow * AST + m0 + msel) * 2);

    const int nrow = (lane & 7) + ((lane >> 4) << 3);
    const int ksel = ((lane >> 3) & 1) * 8;
    uint32_t b_addr0[4];
    #pragma unroll
    for (int j2 = 0; j2 < 4; ++j2)
        b_addr0[j2] = Bs_u + (uint32_t)(((j2 * 16 + nrow) * BST + ksel) * 2);

    float d[8][4];
    #pragma unroll
    for (int j = 0; j < 8; ++j)
        #pragma unroll
        for (int q = 0; q < 4; ++q) d[j][q] = 0.0f;

    for (int ks = 0; ks < KSTEPS; ++ks) {
        uint32_t a[4];
        ldsm_x4_t(a, a_addr0 + (uint32_t)(ks * 16 * AST * 2));
        #pragma unroll
        for (int j2 = 0; j2 < 4; ++j2) {
            uint32_t bbv[4];
            ldsm_x4(bbv, b_addr0[j2] + (uint32_t)(ks * 32));
            mma16816(d[j2 * 2],     a, bbv[0], bbv[1]);
            mma16816(d[j2 * 2 + 1], a, bbv[2], bbv[3]);
        }
    }

    __syncthreads();
    float* stg = reinterpret_cast<float*>(k2_smem);              // [NBn][OST]
    const int g  = lane >> 2;
    const int tp = lane & 3;
    #pragma unroll
    for (int j = 0; j < 8; ++j) {
        int n = j * 8 + 2 * tp;
        int t = m0 + g;
        stg[n * OST + t]           = d[j][0];
        stg[(n + 1) * OST + t]     = d[j][1];
        stg[n * OST + t + 8]       = d[j][2];
        stg[(n + 1) * OST + t + 8] = d[j][3];
    }
    __syncthreads();

    const int tmax = Tn - t0;
    float* ob = out + (size_t)b * NBn * Tn + t0;
    #pragma unroll
    for (int it = 0; it < 8; ++it) {
        int idx = tid + it * 256;
        int n = idx >> 5;
        int c = (idx & 31) * 4;
        if (c < tmax) {
            float4 v = *reinterpret_cast<float4*>(stg + n * OST + c);
            v.x = tanh_fast(v.x); v.y = tanh_fast(v.y);
            v.z = tanh_fast(v.z); v.w = tanh_fast(v.w);
            *reinterpret_cast<float4*>(ob + (size_t)n * Tn + c) = v;
        }
    }
}

// ============================================================
extern "C" void kernel_launch(void* const* d_in, const int* in_sizes, int n_in,
                              void* d_out, int out_size)
{
    const float* mag = (const float*)d_in[0];
    const float* fb  = (const float*)d_in[1];
    const float* ns  = (const float*)d_in[2];
    const float* rr  = (const float*)d_in[3];
    const float* rf  = (const float*)d_in[4];
    float* out = (float*)d_out;

    cudaFuncSetAttribute(band_kernel, cudaFuncAttributeMaxDynamicSharedMemorySize, SMEM_TOTAL);

    fbconv_kernel<<<8, 256>>>(fb);

    int nthreads = Bn * Fn * NCH;
    scan_kernel<<<(nthreads + 255) / 256, 256>>>(mag, ns, rr, rf);

    dim3 grid((Tn + TTILE - 1) / TTILE, Bn);   // 63 x 16
    band_kernel<<<grid, 256, SMEM_TOTAL>>>(out);
}